// round 8
// baseline (speedup 1.0000x reference)
#include <cuda_runtime.h>
#include <cuda_bf16.h>
#include <math.h>
#include <stdint.h>

#define N_PIX  16384
#define BATCH  8

typedef __nv_bfloat16 bf16;

// ---------------- scratch (static device globals; no allocation) ----------------
__device__ __align__(16) float g_part[64 * 8 * 64 * 64];
__device__ __align__(16) float g_rs  [4096 * 512];     // per-(k-row, 32px-group) exp sums
__device__ __align__(16) float g_sinv[4096];           // 1 / rowsum

__device__ __align__(16) bf16 g_fhi [(size_t)BATCH * 256 * N_PIX];
__device__ __align__(16) bf16 g_flo [(size_t)BATCH * 256 * N_PIX];
__device__ __align__(16) bf16 g_dwhi[(size_t)BATCH * 256 * N_PIX];
__device__ __align__(16) bf16 g_dwlo[(size_t)BATCH * 256 * N_PIX];
__device__ __align__(16) bf16 g_qhi [(size_t)BATCH * 512 * N_PIX];
__device__ __align__(16) bf16 g_qlo [(size_t)BATCH * 512 * N_PIX];
__device__ __align__(16) bf16 g_khi [(size_t)BATCH * 512 * N_PIX];   // exp(k) planes
__device__ __align__(16) bf16 g_klo [(size_t)BATCH * 512 * N_PIX];
__device__ __align__(16) bf16 g_vhi [(size_t)BATCH * 512 * N_PIX];
__device__ __align__(16) bf16 g_vlo [(size_t)BATCH * 512 * N_PIX];
__device__ __align__(16) bf16 g_avhi[(size_t)BATCH * 512 * N_PIX];
__device__ __align__(16) bf16 g_avlo[(size_t)BATCH * 512 * N_PIX];
__device__ __align__(16) bf16 g_ctxhi[64 * 64 * 64];
__device__ __align__(16) bf16 g_ctxlo[64 * 64 * 64];
__device__ __align__(16) bf16 g_wqhi [512 * 256],  g_wqlo [512 * 256];
__device__ __align__(16) bf16 g_wpwhi[1024 * 256], g_wpwlo[1024 * 256];
__device__ __align__(16) bf16 g_wohi [256 * 512],  g_wolo [256 * 512];

// ---------------- helpers ----------------
__device__ __forceinline__ float gelu_exact(float x) { return x * normcdff(x); }
__device__ __forceinline__ void fsplit(float x, bf16& h, bf16& l) {
    h = __float2bfloat16_rn(x);
    l = __float2bfloat16_rn(x - __bfloat162float(h));
}
__device__ __forceinline__ uint32_t pack2(bf16 a, bf16 b) {
    __nv_bfloat162 t; t.x = a; t.y = b;
    return *reinterpret_cast<uint32_t*>(&t);
}
__device__ __forceinline__ void mma_bf16(float d[4], const uint32_t a[4], const uint32_t b[2]) {
    asm volatile("mma.sync.aligned.m16n8k16.row.col.f32.bf16.bf16.f32 "
                 "{%0,%1,%2,%3}, {%4,%5,%6,%7}, {%8,%9}, {%0,%1,%2,%3};"
                 : "+f"(d[0]), "+f"(d[1]), "+f"(d[2]), "+f"(d[3])
                 : "r"(a[0]), "r"(a[1]), "r"(a[2]), "r"(a[3]), "r"(b[0]), "r"(b[1]));
}
__device__ __forceinline__ void ldsm4(uint32_t r[4], uint32_t addr) {
    asm volatile("ldmatrix.sync.aligned.m8n8.x4.shared.b16 {%0,%1,%2,%3}, [%4];"
                 : "=r"(r[0]), "=r"(r[1]), "=r"(r[2]), "=r"(r[3]) : "r"(addr));
}
__device__ __forceinline__ void ldsm4t(uint32_t r[4], uint32_t addr) {
    asm volatile("ldmatrix.sync.aligned.m8n8.x4.trans.shared.b16 {%0,%1,%2,%3}, [%4];"
                 : "=r"(r[0]), "=r"(r[1]), "=r"(r[2]), "=r"(r[3]) : "r"(addr));
}
__device__ __forceinline__ uint32_t s2u(const void* p) {
    return (uint32_t)__cvta_generic_to_shared(p);
}
__device__ __forceinline__ void cpa16(uint32_t dst, const void* src) {
    asm volatile("cp.async.cg.shared.global [%0], [%1], 16;" :: "r"(dst), "l"(src));
}
__device__ __forceinline__ void cp_commit() {
    asm volatile("cp.async.commit_group;");
}
template <int N>
__device__ __forceinline__ void cp_wait() {
    asm volatile("cp.async.wait_group %0;" :: "n"(N));
}

// ---------------- weight convert: fp32 -> bf16 hi/lo ----------------
__global__ void k_cvt(const float* __restrict__ x, bf16* __restrict__ hi,
                      bf16* __restrict__ lo, int n)
{
    int i = blockIdx.x * 256 + threadIdx.x;
    if (i < n) { bf16 h, l; fsplit(x[i], h, l); hi[i] = h; lo[i] = l; }
}

// ---------------- depthwise 3x3 (pad 1); 4 px/thread; emit dw & fmap hi/lo ----------------
__global__ void __launch_bounds__(256) k_dwconv(const float* __restrict__ in,
                                                const float* __restrict__ wdw)
{
    int plane = blockIdx.y;              // b*256 + c
    int c = plane & 255;
    const float* ip = in + (size_t)plane * N_PIX;

    float w[9];
#pragma unroll
    for (int k = 0; k < 9; ++k) w[k] = __ldg(wdw + c * 9 + k);

    int p4 = (blockIdx.x * 256 + threadIdx.x) * 4;
    int y = p4 >> 7, x0 = p4 & 127;

    float L[3][6];
#pragma unroll
    for (int r = 0; r < 3; ++r) {
        int yy = y + r - 1;
        if (yy < 0 || yy > 127) {
#pragma unroll
            for (int j = 0; j < 6; ++j) L[r][j] = 0.f;
        } else {
            const float* rp = ip + yy * 128 + x0;
            float4 f = *(const float4*)rp;
            L[r][1] = f.x; L[r][2] = f.y; L[r][3] = f.z; L[r][4] = f.w;
            L[r][0] = (x0 > 0)   ? __ldg(rp - 1) : 0.f;
            L[r][5] = (x0 < 124) ? __ldg(rp + 4) : 0.f;
        }
    }

    bf16 h[4], l[4];
    size_t o = (size_t)plane * N_PIX + p4;
#pragma unroll
    for (int i = 0; i < 4; ++i) {
        float s = 0.f;
#pragma unroll
        for (int r = 0; r < 3; ++r)
#pragma unroll
            for (int dx = 0; dx < 3; ++dx)
                s += L[r][i + dx] * w[r * 3 + dx];
        fsplit(s, h[i], l[i]);
    }
    *(uint2*)(g_dwhi + o) = make_uint2(pack2(h[0], h[1]), pack2(h[2], h[3]));
    *(uint2*)(g_dwlo + o) = make_uint2(pack2(l[0], l[1]), pack2(l[2], l[3]));
#pragma unroll
    for (int i = 0; i < 4; ++i) fsplit(L[1][1 + i], h[i], l[i]);
    *(uint2*)(g_fhi + o) = make_uint2(pack2(h[0], h[1]), pack2(h[2], h[3]));
    *(uint2*)(g_flo + o) = make_uint2(pack2(l[0], l[1]), pack2(l[2], l[3]));
}

// ---------------- split-bf16 tensor-core GEMM with 2-stage cp.async pipeline ----------------
// Y[o,p] = sum_c A[o,c] * X[c,p].  A hi/lo row-major [O,C]; X hi/lo [C,N_PIX].
// Grid: (O/BM, 128, z) — o-blocks fastest so concurrent CTAs share X tiles in L2.
// MODE: 0 fp32 out, 1 hl out, 2 gelu+hl, 3 bias+fp32, 4 softmax-d(64)+scale+hl,
//       5 exp+hl+partial row sums (softmax-N numerator; normalizer folded later).
template <int BM, int MODE>
__global__ void __launch_bounds__(256, 2) k_mma_gemm(
    const bf16* __restrict__ Ahi, const bf16* __restrict__ Alo,
    const bf16* __restrict__ Bhi, const bf16* __restrict__ Blo,
    const float* __restrict__ bias, float* __restrict__ rs,
    float* __restrict__ Yf, bf16* __restrict__ Yhi, bf16* __restrict__ Ylo,
    int C, long long as_, long long xs, long long ys)
{
    constexpr int BN = 128, BK = 32, AP = 40, BP = 136;
    constexpr int WM = BM / 2, MT = WM / 16;
    constexpr uint32_t APl = BM * AP * 2;
    constexpr uint32_t BPl = BK * BP * 2;

    extern __shared__ __align__(16) bf16 smp[];

    const int t = threadIdx.x, warp = t >> 5, lane = t & 31;
    const int wm = warp & 1, wn = warp >> 1;
    const int g = lane >> 2, tig = lane & 3;
    const int o0 = blockIdx.x * BM, pblk = blockIdx.y * BN;
    const long long z = blockIdx.z;
    const bf16* AH = Ahi + z * as_;
    const bf16* AL = Alo + z * as_;
    const bf16* XH = Bhi + z * xs;
    const bf16* XL = Blo + z * xs;

    const uint32_t Abase = s2u(smp);
    const uint32_t Bbase = Abase + 4 * APl;

#define LOAD_STAGE(st, c0v) do {                                              \
    uint32_t aD = Abase + (uint32_t)(st) * 2 * APl;                           \
    uint32_t bD = Bbase + (uint32_t)(st) * 2 * BPl;                           \
    for (int i = t; i < BM * 4; i += 256) {                                   \
        int m_ = i >> 2, kq = (i & 3) * 8;                                    \
        size_t src = (size_t)(o0 + m_) * C + (c0v) + kq;                      \
        uint32_t d_ = (uint32_t)(m_ * AP + kq) * 2;                           \
        cpa16(aD + d_, AH + src);                                             \
        cpa16(aD + APl + d_, AL + src);                                       \
    }                                                                         \
    for (int i = t; i < 512; i += 256) {                                      \
        int cc = i >> 4, pq = (i & 15) * 8;                                   \
        size_t src = (size_t)((c0v) + cc) * N_PIX + pblk + pq;                \
        uint32_t d_ = (uint32_t)(cc * BP + pq) * 2;                           \
        cpa16(bD + d_, XH + src);                                             \
        cpa16(bD + BPl + d_, XL + src);                                       \
    }                                                                         \
    cp_commit();                                                              \
} while (0)

    float acc[MT][4][4];
#pragma unroll
    for (int m = 0; m < MT; ++m)
#pragma unroll
        for (int n = 0; n < 4; ++n)
#pragma unroll
            for (int r = 0; r < 4; ++r) acc[m][n][r] = 0.f;

    const int l15 = lane & 15;
    const int hi8 = (lane >> 4) * 8;

    const int T = C >> 5;
    LOAD_STAGE(0, 0);

    for (int it = 0; it < T; ++it) {
        const int st = it & 1;
        if (it + 1 < T) { LOAD_STAGE(st ^ 1, (it + 1) * BK); cp_wait<1>(); }
        else cp_wait<0>();
        __syncthreads();

        const uint32_t a0 = Abase + (uint32_t)st * 2 * APl;
        const uint32_t a1 = a0 + APl;
        const uint32_t b0 = Bbase + (uint32_t)st * 2 * BPl;
        const uint32_t b1 = b0 + BPl;

#pragma unroll
        for (int ks = 0; ks < BK; ks += 16) {
            uint32_t bh_[4][2], bl_[4][2], r[4];
#pragma unroll
            for (int nn = 0; nn < 2; ++nn) {
                uint32_t off = (uint32_t)((ks + l15) * BP + wn * 32 + nn * 16 + hi8) * 2;
                ldsm4t(r, b0 + off);
                bh_[nn*2][0] = r[0]; bh_[nn*2][1] = r[1];
                bh_[nn*2+1][0] = r[2]; bh_[nn*2+1][1] = r[3];
                ldsm4t(r, b1 + off);
                bl_[nn*2][0] = r[0]; bl_[nn*2][1] = r[1];
                bl_[nn*2+1][0] = r[2]; bl_[nn*2+1][1] = r[3];
            }
#pragma unroll
            for (int mt = 0; mt < MT; ++mt) {
                uint32_t ah[4], al[4];
                uint32_t off = (uint32_t)((wm * WM + mt * 16 + l15) * AP + ks + hi8) * 2;
                ldsm4(ah, a0 + off);
                ldsm4(al, a1 + off);
#pragma unroll
                for (int nt = 0; nt < 4; ++nt) {
                    mma_bf16(acc[mt][nt], ah, bh_[nt]);
                    mma_bf16(acc[mt][nt], al, bh_[nt]);
                    mma_bf16(acc[mt][nt], ah, bl_[nt]);
                }
            }
        }
        __syncthreads();
    }
#undef LOAD_STAGE

    if (MODE == 4) {
        // softmax over the 64 rows of this warp-half (one head), per pixel column; *1/8
        float sc[8];
#pragma unroll
        for (int nt = 0; nt < 4; ++nt)
#pragma unroll
            for (int c = 0; c < 2; ++c) {
                float m = -3.4e38f;
#pragma unroll
                for (int mt = 0; mt < MT; ++mt) {
                    m = fmaxf(m, acc[mt][nt][c]);
                    m = fmaxf(m, acc[mt][nt][2 + c]);
                }
                m = fmaxf(m, __shfl_xor_sync(0xffffffffu, m, 4));
                m = fmaxf(m, __shfl_xor_sync(0xffffffffu, m, 8));
                m = fmaxf(m, __shfl_xor_sync(0xffffffffu, m, 16));
                float s = 0.f;
#pragma unroll
                for (int mt = 0; mt < MT; ++mt) {
                    float e0 = expf(acc[mt][nt][c] - m);
                    float e1 = expf(acc[mt][nt][2 + c] - m);
                    acc[mt][nt][c] = e0; acc[mt][nt][2 + c] = e1;
                    s += e0 + e1;
                }
                s += __shfl_xor_sync(0xffffffffu, s, 4);
                s += __shfl_xor_sync(0xffffffffu, s, 8);
                s += __shfl_xor_sync(0xffffffffu, s, 16);
                sc[nt * 2 + c] = 0.125f / s;
            }
#pragma unroll
        for (int mt = 0; mt < MT; ++mt)
#pragma unroll
            for (int h2 = 0; h2 < 2; ++h2) {
                int rrow = o0 + wm * WM + mt * 16 + g + h2 * 8;
#pragma unroll
                for (int nt = 0; nt < 4; ++nt) {
                    int p = pblk + wn * 32 + nt * 8 + tig * 2;
                    float v0 = acc[mt][nt][h2 * 2 + 0] * sc[nt * 2 + 0];
                    float v1 = acc[mt][nt][h2 * 2 + 1] * sc[nt * 2 + 1];
                    size_t o = (size_t)rrow * N_PIX + p;
                    bf16 h0, l0, h1, l1;
                    fsplit(v0, h0, l0); fsplit(v1, h1, l1);
                    *(uint32_t*)(Yhi + z * ys + o) = pack2(h0, h1);
                    *(uint32_t*)(Ylo + z * ys + o) = pack2(l0, l1);
                }
            }
        return;
    }

    if (MODE == 5) {
        // exp(acc); store hl planes; per-(row, 32px) partial sums for softmax-N normalizer
#pragma unroll
        for (int mt = 0; mt < MT; ++mt)
#pragma unroll
            for (int h2 = 0; h2 < 2; ++h2) {
                int rrow = o0 + wm * WM + mt * 16 + g + h2 * 8;
                float s_th = 0.f;
#pragma unroll
                for (int nt = 0; nt < 4; ++nt) {
                    int p = pblk + wn * 32 + nt * 8 + tig * 2;
                    float v0 = expf(acc[mt][nt][h2 * 2 + 0]);
                    float v1 = expf(acc[mt][nt][h2 * 2 + 1]);
                    s_th += v0 + v1;
                    size_t o = (size_t)rrow * N_PIX + p;
                    bf16 h0, l0, h1, l1;
                    fsplit(v0, h0, l0); fsplit(v1, h1, l1);
                    *(uint32_t*)(Yhi + z * ys + o) = pack2(h0, h1);
                    *(uint32_t*)(Ylo + z * ys + o) = pack2(l0, l1);
                }
                s_th += __shfl_xor_sync(0xffffffffu, s_th, 1);
                s_th += __shfl_xor_sync(0xffffffffu, s_th, 2);
                if (tig == 0)
                    rs[((size_t)z * 512 + rrow) * 512 + blockIdx.y * 4 + wn] = s_th;
            }
        return;
    }

#pragma unroll
    for (int mt = 0; mt < MT; ++mt) {
#pragma unroll
        for (int h2 = 0; h2 < 2; ++h2) {
            int rrow = o0 + wm * WM + mt * 16 + g + h2 * 8;
            float bb = (MODE == 3) ? __ldg(&bias[rrow]) : 0.f;
#pragma unroll
            for (int nt = 0; nt < 4; ++nt) {
                int p = pblk + wn * 32 + nt * 8 + tig * 2;
                float v0 = acc[mt][nt][h2 * 2 + 0] + bb;
                float v1 = acc[mt][nt][h2 * 2 + 1] + bb;
                size_t o = (size_t)rrow * N_PIX + p;
                if (MODE == 0 || MODE == 3) {
                    *(float2*)(Yf + z * ys + o) = make_float2(v0, v1);
                } else {
                    if (MODE == 2) { v0 = gelu_exact(v0); v1 = gelu_exact(v1); }
                    bf16 h0, l0, h1, l1;
                    fsplit(v0, h0, l0); fsplit(v1, h1, l1);
                    *(uint32_t*)(Yhi + z * ys + o) = pack2(h0, h1);
                    *(uint32_t*)(Ylo + z * ys + o) = pack2(l0, l1);
                }
            }
        }
    }
}

// ---------------- reduce exp-row partial sums -> 1/S per k-row ----------------
__global__ void __launch_bounds__(256) k_sumred(const float* __restrict__ rs,
                                                float* __restrict__ sinv)
{
    int row = blockIdx.x * 8 + (threadIdx.x >> 5);   // 512 blocks x 8 warps = 4096 rows
    int lane = threadIdx.x & 31;
    const float* p = rs + (size_t)row * 512;
    float s = 0.f;
#pragma unroll
    for (int i = 0; i < 16; ++i) s += p[lane + i * 32];
#pragma unroll
    for (int o = 16; o; o >>= 1) s += __shfl_xor_sync(0xffffffffu, s, o);
    if (lane == 0) sinv[row] = 1.0f / s;
}

// ---------------- context partials (tensor, pipelined): P[bh,s][e][d] ----------------
__global__ void __launch_bounds__(256, 2) k_ctx_t(
    const bf16* __restrict__ khi, const bf16* __restrict__ klo,
    const bf16* __restrict__ vhi, const bf16* __restrict__ vlo,
    float* __restrict__ part)
{
    constexpr int P = 72;
    constexpr uint32_t ASZ = 64 * P * 2;
    extern __shared__ __align__(16) bf16 smp[];

    int t = threadIdx.x, warp = t >> 5, lane = t & 31;
    int wm = warp & 1, wn = warp >> 1;
    int g = lane >> 2, tig = lane & 3;
    int bh = blockIdx.x >> 3, s = blockIdx.x & 7;
    size_t cb = (size_t)bh * 64 * N_PIX + (size_t)s * 2048;

    const uint32_t base = s2u(smp);
#define CARR(st, a) (base + ((uint32_t)(st) * 4 + (a)) * ASZ)

#define CTX_LOAD(st, itv) do {                                                \
    for (int i = t; i < 512; i += 256) {                                      \
        int row = i >> 3, c8 = (i & 7) * 8;                                   \
        size_t src = cb + (size_t)row * N_PIX + (itv) * 64 + c8;              \
        uint32_t d_ = (uint32_t)(row * P + c8) * 2;                           \
        cpa16(CARR(st, 0) + d_, khi + src);                                   \
        cpa16(CARR(st, 1) + d_, klo + src);                                   \
        cpa16(CARR(st, 2) + d_, vhi + src);                                   \
        cpa16(CARR(st, 3) + d_, vlo + src);                                   \
    }                                                                         \
    cp_commit();                                                              \
} while (0)

    float acc[2][2][4];
#pragma unroll
    for (int m = 0; m < 2; ++m)
#pragma unroll
        for (int n = 0; n < 2; ++n)
#pragma unroll
            for (int r = 0; r < 4; ++r) acc[m][n][r] = 0.f;

    const int l15 = lane & 15, hi8 = (lane >> 4) * 8;
    const int bg = lane >> 3, bl = lane & 7;
    const int brow = (bg >> 1) * 8 + bl;
    const int bcol = (bg & 1) * 8;

    CTX_LOAD(0, 0);
    for (int it = 0; it < 32; ++it) {
        int st = it & 1;
        if (it + 1 < 32) { CTX_LOAD(st ^ 1, it + 1); cp_wait<1>(); }
        else cp_wait<0>();
        __syncthreads();

        const uint32_t kB0 = CARR(st, 0), kB1 = CARR(st, 1);
        const uint32_t vB0 = CARR(st, 2), vB1 = CARR(st, 3);

#pragma unroll
        for (int ks = 0; ks < 64; ks += 16) {
            uint32_t bh_[2][2], bl_[2][2], r[4];
            uint32_t boff = (uint32_t)((wn * 16 + brow) * P + ks + bcol) * 2;
            ldsm4(r, kB0 + boff);
            bh_[0][0] = r[0]; bh_[0][1] = r[1]; bh_[1][0] = r[2]; bh_[1][1] = r[3];
            ldsm4(r, kB1 + boff);
            bl_[0][0] = r[0]; bl_[0][1] = r[1]; bl_[1][0] = r[2]; bl_[1][1] = r[3];
#pragma unroll
            for (int mt = 0; mt < 2; ++mt) {
                uint32_t ah[4], al[4];
                uint32_t aoff = (uint32_t)((wm * 32 + mt * 16 + l15) * P + ks + hi8) * 2;
                ldsm4(ah, vB0 + aoff);
                ldsm4(al, vB1 + aoff);
#pragma unroll
                for (int nt = 0; nt < 2; ++nt) {
                    mma_bf16(acc[mt][nt], ah, bh_[nt]);
                    mma_bf16(acc[mt][nt], al, bh_[nt]);
                    mma_bf16(acc[mt][nt], ah, bl_[nt]);
                }
            }
        }
        __syncthreads();
    }
#undef CTX_LOAD
#undef CARR

    size_t ob = (size_t)blockIdx.x * 4096;
#pragma unroll
    for (int mt = 0; mt < 2; ++mt)
#pragma unroll
        for (int h2 = 0; h2 < 2; ++h2) {
            int e = wm * 32 + mt * 16 + g + h2 * 8;
#pragma unroll
            for (int nt = 0; nt < 2; ++nt) {
                int d = wn * 16 + nt * 8 + tig * 2;
                *(float2*)&part[ob + (size_t)e * 64 + d] =
                    make_float2(acc[mt][nt][h2 * 2], acc[mt][nt][h2 * 2 + 1]);
            }
        }
}

// ---------------- reduce partials; normalize by 1/S[d]; emit ctx^T hi/lo ----------------
__global__ void k_ctx_reduce(const float* __restrict__ part, const float* __restrict__ sinv,
                             bf16* __restrict__ chi, bf16* __restrict__ clo)
{
    int i = blockIdx.x * 256 + threadIdx.x;
    int bh = i >> 12, ed = i & 4095;
    int d = ed & 63;
    float s = 0.f;
#pragma unroll
    for (int ss = 0; ss < 8; ++ss)
        s += part[((size_t)bh * 8 + ss) * 4096 + ed];
    s *= sinv[(bh >> 3) * 512 + (bh & 7) * 64 + d];
    bf16 h, l; fsplit(s, h, l);
    chi[i] = h; clo[i] = l;
}

// ---------------- launch ----------------
extern "C" void kernel_launch(void* const* d_in, const int* in_sizes, int n_in,
                              void* d_out, int out_size)
{
    const float* fmap  = (const float*)d_in[0];
    const float* w_q   = (const float*)d_in[1];
    const float* w_dw  = (const float*)d_in[2];
    const float* w_pw  = (const float*)d_in[3];
    const float* w_out = (const float*)d_in[4];
    const float* b_out = (const float*)d_in[5];
    float* out = (float*)d_out;

    float *part, *rs, *sinv;
    bf16 *fhi, *flo, *dwhi, *dwlo, *qhi, *qlo, *khi, *klo, *vhi, *vlo;
    bf16 *avhi, *avlo, *chi, *clo, *wqh, *wql, *wph, *wpl, *woh, *wol;
    cudaGetSymbolAddress((void**)&part, g_part);
    cudaGetSymbolAddress((void**)&rs,   g_rs);
    cudaGetSymbolAddress((void**)&sinv, g_sinv);
    cudaGetSymbolAddress((void**)&fhi,  g_fhi);   cudaGetSymbolAddress((void**)&flo,  g_flo);
    cudaGetSymbolAddress((void**)&dwhi, g_dwhi);  cudaGetSymbolAddress((void**)&dwlo, g_dwlo);
    cudaGetSymbolAddress((void**)&qhi,  g_qhi);   cudaGetSymbolAddress((void**)&qlo,  g_qlo);
    cudaGetSymbolAddress((void**)&khi,  g_khi);   cudaGetSymbolAddress((void**)&klo,  g_klo);
    cudaGetSymbolAddress((void**)&vhi,  g_vhi);   cudaGetSymbolAddress((void**)&vlo,  g_vlo);
    cudaGetSymbolAddress((void**)&avhi, g_avhi);  cudaGetSymbolAddress((void**)&avlo, g_avlo);
    cudaGetSymbolAddress((void**)&chi,  g_ctxhi); cudaGetSymbolAddress((void**)&clo,  g_ctxlo);
    cudaGetSymbolAddress((void**)&wqh,  g_wqhi);  cudaGetSymbolAddress((void**)&wql,  g_wqlo);
    cudaGetSymbolAddress((void**)&wph,  g_wpwhi); cudaGetSymbolAddress((void**)&wpl,  g_wpwlo);
    cudaGetSymbolAddress((void**)&woh,  g_wohi);  cudaGetSymbolAddress((void**)&wol,  g_wolo);

    const int SM128 = 8 * (40 * 128 + 4352);   // 75776 B
    const int SM64  = 8 * (40 * 64 + 4352);    // 55296 B
    const int SMCTX = 2 * 4 * 64 * 72 * 2;     // 73728 B
    cudaFuncSetAttribute(k_mma_gemm<128,4>, cudaFuncAttributeMaxDynamicSharedMemorySize, SM128);
    cudaFuncSetAttribute(k_mma_gemm<128,5>, cudaFuncAttributeMaxDynamicSharedMemorySize, SM128);
    cudaFuncSetAttribute(k_mma_gemm<128,1>, cudaFuncAttributeMaxDynamicSharedMemorySize, SM128);
    cudaFuncSetAttribute(k_mma_gemm<128,3>, cudaFuncAttributeMaxDynamicSharedMemorySize, SM128);
    cudaFuncSetAttribute(k_mma_gemm<64,2>,  cudaFuncAttributeMaxDynamicSharedMemorySize, SM64);
    cudaFuncSetAttribute(k_ctx_t,           cudaFuncAttributeMaxDynamicSharedMemorySize, SMCTX);

    // 0) weight splits
    k_cvt<<<512, 256>>>(w_q, wqh, wql, 512 * 256);
    k_cvt<<<1024, 256>>>(w_pw, wph, wpl, 1024 * 256);
    k_cvt<<<512, 256>>>(w_out, woh, wol, 256 * 512);

    // 1) depthwise 3x3 + fmap/dw hi-lo planes
    k_dwconv<<<dim3(16, BATCH * 256), 256>>>(fmap, w_dw);

    // 2) q = softmax_d(w_q @ fmap) * 1/8  (fused, hl out)
    k_mma_gemm<128, 4><<<dim3(4, 128, 8), 256, SM128>>>(
        wqh, wql, fhi, flo, nullptr, nullptr, nullptr, qhi, qlo,
        256, 0, 256LL * N_PIX, 512LL * N_PIX);

    // 3a) exp(k) = exp(w_pw[0:512] @ dw)  (hl out + partial row sums)
    k_mma_gemm<128, 5><<<dim3(4, 128, 8), 256, SM128>>>(
        wph, wpl, dwhi, dwlo, nullptr, rs, nullptr, khi, klo,
        256, 0, 256LL * N_PIX, 512LL * N_PIX);

    // 3b) v = w_pw[512:1024] @ dw  (hl out)
    k_mma_gemm<128, 1><<<dim3(4, 128, 8), 256, SM128>>>(
        wph + 512 * 256, wpl + 512 * 256, dwhi, dwlo, nullptr, nullptr,
        nullptr, vhi, vlo, 256, 0, 256LL * N_PIX, 512LL * N_PIX);

    // 4) softmax-N normalizer: 1/S per k-row
    k_sumred<<<512, 256>>>(rs, sinv);

    // 5) context: pipelined tensor split-K partials + normalize-reduce
    k_ctx_t<<<512, 256, SMCTX>>>(khi, klo, vhi, vlo, part);
    k_ctx_reduce<<<1024, 256>>>(part, sinv, chi, clo);

    // 6) av = gelu(ctx^T @ q)  batched over 64 (b,h)  (hl out)
    k_mma_gemm<64, 2><<<dim3(1, 128, 64), 256, SM64>>>(
        chi, clo, qhi, qlo, nullptr, nullptr, nullptr, avhi, avlo,
        64, 4096LL, 64LL * N_PIX, 64LL * N_PIX);

    // 7) out = w_out @ av + b_out  (fp32 + bias)
    k_mma_gemm<128, 3><<<dim3(2, 128, 8), 256, SM128>>>(
        woh, wol, avhi, avlo, b_out, nullptr, out, nullptr, nullptr,
        512, 0, 512LL * N_PIX, 256LL * N_PIX);
}

// round 9
// speedup vs baseline: 1.4915x; 1.4915x over previous
#include <cuda_runtime.h>
#include <cuda_bf16.h>
#include <math.h>
#include <stdint.h>

#define N_PIX  16384
#define BATCH  8

typedef __nv_bfloat16 bf16;

// ---------------- scratch (static device globals; no allocation) ----------------
__device__ __align__(16) float g_part[64 * 8 * 64 * 64];
__device__ __align__(16) float g_rs  [4096 * 512];     // per-(k-row, 32px-group) exp sums
__device__ __align__(16) float g_sinv[4096];           // 1 / rowsum

__device__ __align__(16) bf16 g_fhi [(size_t)BATCH * 256 * N_PIX];
__device__ __align__(16) bf16 g_flo [(size_t)BATCH * 256 * N_PIX];
__device__ __align__(16) bf16 g_dwhi[(size_t)BATCH * 256 * N_PIX];
__device__ __align__(16) bf16 g_dwlo[(size_t)BATCH * 256 * N_PIX];
__device__ __align__(16) bf16 g_qhi [(size_t)BATCH * 512 * N_PIX];
__device__ __align__(16) bf16 g_qlo [(size_t)BATCH * 512 * N_PIX];
__device__ __align__(16) bf16 g_khi [(size_t)BATCH * 512 * N_PIX];   // exp(k) planes
__device__ __align__(16) bf16 g_klo [(size_t)BATCH * 512 * N_PIX];
__device__ __align__(16) bf16 g_vhi [(size_t)BATCH * 512 * N_PIX];
__device__ __align__(16) bf16 g_vlo [(size_t)BATCH * 512 * N_PIX];
__device__ __align__(16) bf16 g_avhi[(size_t)BATCH * 512 * N_PIX];
__device__ __align__(16) bf16 g_avlo[(size_t)BATCH * 512 * N_PIX];
__device__ __align__(16) bf16 g_ctxhi[64 * 64 * 64];
__device__ __align__(16) bf16 g_ctxlo[64 * 64 * 64];
__device__ __align__(16) bf16 g_wqhi [512 * 256],  g_wqlo [512 * 256];
__device__ __align__(16) bf16 g_wpwhi[1024 * 256], g_wpwlo[1024 * 256];
__device__ __align__(16) bf16 g_wohi [256 * 512],  g_wolo [256 * 512];

// ---------------- helpers ----------------
__device__ __forceinline__ float gelu_exact(float x) { return x * normcdff(x); }
__device__ __forceinline__ void fsplit(float x, bf16& h, bf16& l) {
    h = __float2bfloat16_rn(x);
    l = __float2bfloat16_rn(x - __bfloat162float(h));
}
__device__ __forceinline__ uint32_t pack2(bf16 a, bf16 b) {
    __nv_bfloat162 t; t.x = a; t.y = b;
    return *reinterpret_cast<uint32_t*>(&t);
}
__device__ __forceinline__ void mma_bf16(float d[4], const uint32_t a[4], const uint32_t b[2]) {
    asm volatile("mma.sync.aligned.m16n8k16.row.col.f32.bf16.bf16.f32 "
                 "{%0,%1,%2,%3}, {%4,%5,%6,%7}, {%8,%9}, {%0,%1,%2,%3};"
                 : "+f"(d[0]), "+f"(d[1]), "+f"(d[2]), "+f"(d[3])
                 : "r"(a[0]), "r"(a[1]), "r"(a[2]), "r"(a[3]), "r"(b[0]), "r"(b[1]));
}
__device__ __forceinline__ void ldsm4(uint32_t r[4], uint32_t addr) {
    asm volatile("ldmatrix.sync.aligned.m8n8.x4.shared.b16 {%0,%1,%2,%3}, [%4];"
                 : "=r"(r[0]), "=r"(r[1]), "=r"(r[2]), "=r"(r[3]) : "r"(addr));
}
__device__ __forceinline__ void ldsm4t(uint32_t r[4], uint32_t addr) {
    asm volatile("ldmatrix.sync.aligned.m8n8.x4.trans.shared.b16 {%0,%1,%2,%3}, [%4];"
                 : "=r"(r[0]), "=r"(r[1]), "=r"(r[2]), "=r"(r[3]) : "r"(addr));
}
__device__ __forceinline__ uint32_t s2u(const void* p) {
    return (uint32_t)__cvta_generic_to_shared(p);
}
__device__ __forceinline__ void cpa16(uint32_t dst, const void* src) {
    asm volatile("cp.async.cg.shared.global [%0], [%1], 16;" :: "r"(dst), "l"(src));
}
__device__ __forceinline__ void cp_commit() {
    asm volatile("cp.async.commit_group;");
}
template <int N>
__device__ __forceinline__ void cp_wait() {
    asm volatile("cp.async.wait_group %0;" :: "n"(N));
}

// ---------------- weight convert: fp32 -> bf16 hi/lo ----------------
__global__ void k_cvt(const float* __restrict__ x, bf16* __restrict__ hi,
                      bf16* __restrict__ lo, int n)
{
    int i = blockIdx.x * 256 + threadIdx.x;
    if (i < n) { bf16 h, l; fsplit(x[i], h, l); hi[i] = h; lo[i] = l; }
}

// ---------------- depthwise 3x3 (pad 1); 4 px/thread; emit dw & fmap hi/lo ----------------
__global__ void __launch_bounds__(256) k_dwconv(const float* __restrict__ in,
                                                const float* __restrict__ wdw)
{
    int plane = blockIdx.y;              // b*256 + c
    int c = plane & 255;
    const float* ip = in + (size_t)plane * N_PIX;

    float w[9];
#pragma unroll
    for (int k = 0; k < 9; ++k) w[k] = __ldg(wdw + c * 9 + k);

    int p4 = (blockIdx.x * 256 + threadIdx.x) * 4;
    int y = p4 >> 7, x0 = p4 & 127;

    float L[3][6];
#pragma unroll
    for (int r = 0; r < 3; ++r) {
        int yy = y + r - 1;
        if (yy < 0 || yy > 127) {
#pragma unroll
            for (int j = 0; j < 6; ++j) L[r][j] = 0.f;
        } else {
            const float* rp = ip + yy * 128 + x0;
            float4 f = *(const float4*)rp;
            L[r][1] = f.x; L[r][2] = f.y; L[r][3] = f.z; L[r][4] = f.w;
            L[r][0] = (x0 > 0)   ? __ldg(rp - 1) : 0.f;
            L[r][5] = (x0 < 124) ? __ldg(rp + 4) : 0.f;
        }
    }

    bf16 h[4], l[4];
    size_t o = (size_t)plane * N_PIX + p4;
#pragma unroll
    for (int i = 0; i < 4; ++i) {
        float s = 0.f;
#pragma unroll
        for (int r = 0; r < 3; ++r)
#pragma unroll
            for (int dx = 0; dx < 3; ++dx)
                s += L[r][i + dx] * w[r * 3 + dx];
        fsplit(s, h[i], l[i]);
    }
    *(uint2*)(g_dwhi + o) = make_uint2(pack2(h[0], h[1]), pack2(h[2], h[3]));
    *(uint2*)(g_dwlo + o) = make_uint2(pack2(l[0], l[1]), pack2(l[2], l[3]));
#pragma unroll
    for (int i = 0; i < 4; ++i) fsplit(L[1][1 + i], h[i], l[i]);
    *(uint2*)(g_fhi + o) = make_uint2(pack2(h[0], h[1]), pack2(h[2], h[3]));
    *(uint2*)(g_flo + o) = make_uint2(pack2(l[0], l[1]), pack2(l[2], l[3]));
}

// ---------------- split-bf16 tensor-core GEMM with 2-stage cp.async pipeline ----------------
// Y[o,p] = sum_c A[o,c] * X[c,p].  A hi/lo row-major [O,C]; X hi/lo [C,N_PIX].
// Grid: (128 pixel-blocks, O/BM, z) — pixel-major order (round-7 layout; o-major regressed).
// MODE: 0 fp32 out, 1 hl out, 2 gelu+hl, 3 bias+fp32, 4 softmax-d(64)+scale+hl,
//       5 exp+hl+partial row sums (softmax-N numerator; normalizer folded into ctx reduce).
template <int BM, int MODE>
__global__ void __launch_bounds__(256, 2) k_mma_gemm(
    const bf16* __restrict__ Ahi, const bf16* __restrict__ Alo,
    const bf16* __restrict__ Bhi, const bf16* __restrict__ Blo,
    const float* __restrict__ bias, float* __restrict__ rs,
    float* __restrict__ Yf, bf16* __restrict__ Yhi, bf16* __restrict__ Ylo,
    int C, long long as_, long long xs, long long ys)
{
    constexpr int BN = 128, BK = 32, AP = 40, BP = 136;
    constexpr int WM = BM / 2, MT = WM / 16;
    constexpr uint32_t APl = BM * AP * 2;
    constexpr uint32_t BPl = BK * BP * 2;

    extern __shared__ __align__(16) bf16 smp[];

    const int t = threadIdx.x, warp = t >> 5, lane = t & 31;
    const int wm = warp & 1, wn = warp >> 1;
    const int g = lane >> 2, tig = lane & 3;
    const int pblk = blockIdx.x * BN, o0 = blockIdx.y * BM;
    const long long z = blockIdx.z;
    const bf16* AH = Ahi + z * as_;
    const bf16* AL = Alo + z * as_;
    const bf16* XH = Bhi + z * xs;
    const bf16* XL = Blo + z * xs;

    const uint32_t Abase = s2u(smp);
    const uint32_t Bbase = Abase + 4 * APl;

#define LOAD_STAGE(st, c0v) do {                                              \
    uint32_t aD = Abase + (uint32_t)(st) * 2 * APl;                           \
    uint32_t bD = Bbase + (uint32_t)(st) * 2 * BPl;                           \
    for (int i = t; i < BM * 4; i += 256) {                                   \
        int m_ = i >> 2, kq = (i & 3) * 8;                                    \
        size_t src = (size_t)(o0 + m_) * C + (c0v) + kq;                      \
        uint32_t d_ = (uint32_t)(m_ * AP + kq) * 2;                           \
        cpa16(aD + d_, AH + src);                                             \
        cpa16(aD + APl + d_, AL + src);                                       \
    }                                                                         \
    for (int i = t; i < 512; i += 256) {                                      \
        int cc = i >> 4, pq = (i & 15) * 8;                                   \
        size_t src = (size_t)((c0v) + cc) * N_PIX + pblk + pq;                \
        uint32_t d_ = (uint32_t)(cc * BP + pq) * 2;                           \
        cpa16(bD + d_, XH + src);                                             \
        cpa16(bD + BPl + d_, XL + src);                                       \
    }                                                                         \
    cp_commit();                                                              \
} while (0)

    float acc[MT][4][4];
#pragma unroll
    for (int m = 0; m < MT; ++m)
#pragma unroll
        for (int n = 0; n < 4; ++n)
#pragma unroll
            for (int r = 0; r < 4; ++r) acc[m][n][r] = 0.f;

    const int l15 = lane & 15;
    const int hi8 = (lane >> 4) * 8;

    const int T = C >> 5;
    LOAD_STAGE(0, 0);

    for (int it = 0; it < T; ++it) {
        const int st = it & 1;
        if (it + 1 < T) { LOAD_STAGE(st ^ 1, (it + 1) * BK); cp_wait<1>(); }
        else cp_wait<0>();
        __syncthreads();

        const uint32_t a0 = Abase + (uint32_t)st * 2 * APl;
        const uint32_t a1 = a0 + APl;
        const uint32_t b0 = Bbase + (uint32_t)st * 2 * BPl;
        const uint32_t b1 = b0 + BPl;

#pragma unroll
        for (int ks = 0; ks < BK; ks += 16) {
            uint32_t bh_[4][2], bl_[4][2], r[4];
#pragma unroll
            for (int nn = 0; nn < 2; ++nn) {
                uint32_t off = (uint32_t)((ks + l15) * BP + wn * 32 + nn * 16 + hi8) * 2;
                ldsm4t(r, b0 + off);
                bh_[nn*2][0] = r[0]; bh_[nn*2][1] = r[1];
                bh_[nn*2+1][0] = r[2]; bh_[nn*2+1][1] = r[3];
                ldsm4t(r, b1 + off);
                bl_[nn*2][0] = r[0]; bl_[nn*2][1] = r[1];
                bl_[nn*2+1][0] = r[2]; bl_[nn*2+1][1] = r[3];
            }
#pragma unroll
            for (int mt = 0; mt < MT; ++mt) {
                uint32_t ah[4], al[4];
                uint32_t off = (uint32_t)((wm * WM + mt * 16 + l15) * AP + ks + hi8) * 2;
                ldsm4(ah, a0 + off);
                ldsm4(al, a1 + off);
#pragma unroll
                for (int nt = 0; nt < 4; ++nt) {
                    mma_bf16(acc[mt][nt], ah, bh_[nt]);
                    mma_bf16(acc[mt][nt], al, bh_[nt]);
                    mma_bf16(acc[mt][nt], ah, bl_[nt]);
                }
            }
        }
        __syncthreads();
    }
#undef LOAD_STAGE

    if (MODE == 4) {
        // softmax over the 64 rows of this warp-half (one head), per pixel column; *1/8
        float sc[8];
#pragma unroll
        for (int nt = 0; nt < 4; ++nt)
#pragma unroll
            for (int c = 0; c < 2; ++c) {
                float m = -3.4e38f;
#pragma unroll
                for (int mt = 0; mt < MT; ++mt) {
                    m = fmaxf(m, acc[mt][nt][c]);
                    m = fmaxf(m, acc[mt][nt][2 + c]);
                }
                m = fmaxf(m, __shfl_xor_sync(0xffffffffu, m, 4));
                m = fmaxf(m, __shfl_xor_sync(0xffffffffu, m, 8));
                m = fmaxf(m, __shfl_xor_sync(0xffffffffu, m, 16));
                float s = 0.f;
#pragma unroll
                for (int mt = 0; mt < MT; ++mt) {
                    float e0 = expf(acc[mt][nt][c] - m);
                    float e1 = expf(acc[mt][nt][2 + c] - m);
                    acc[mt][nt][c] = e0; acc[mt][nt][2 + c] = e1;
                    s += e0 + e1;
                }
                s += __shfl_xor_sync(0xffffffffu, s, 4);
                s += __shfl_xor_sync(0xffffffffu, s, 8);
                s += __shfl_xor_sync(0xffffffffu, s, 16);
                sc[nt * 2 + c] = 0.125f / s;
            }
#pragma unroll
        for (int mt = 0; mt < MT; ++mt)
#pragma unroll
            for (int h2 = 0; h2 < 2; ++h2) {
                int rrow = o0 + wm * WM + mt * 16 + g + h2 * 8;
#pragma unroll
                for (int nt = 0; nt < 4; ++nt) {
                    int p = pblk + wn * 32 + nt * 8 + tig * 2;
                    float v0 = acc[mt][nt][h2 * 2 + 0] * sc[nt * 2 + 0];
                    float v1 = acc[mt][nt][h2 * 2 + 1] * sc[nt * 2 + 1];
                    size_t o = (size_t)rrow * N_PIX + p;
                    bf16 h0, l0, h1, l1;
                    fsplit(v0, h0, l0); fsplit(v1, h1, l1);
                    *(uint32_t*)(Yhi + z * ys + o) = pack2(h0, h1);
                    *(uint32_t*)(Ylo + z * ys + o) = pack2(l0, l1);
                }
            }
        return;
    }

    if (MODE == 5) {
        // exp(acc); store hl planes; per-(row, 32px) partial sums for softmax-N normalizer
#pragma unroll
        for (int mt = 0; mt < MT; ++mt)
#pragma unroll
            for (int h2 = 0; h2 < 2; ++h2) {
                int rrow = o0 + wm * WM + mt * 16 + g + h2 * 8;
                float s_th = 0.f;
#pragma unroll
                for (int nt = 0; nt < 4; ++nt) {
                    int p = pblk + wn * 32 + nt * 8 + tig * 2;
                    float v0 = expf(acc[mt][nt][h2 * 2 + 0]);
                    float v1 = expf(acc[mt][nt][h2 * 2 + 1]);
                    s_th += v0 + v1;
                    size_t o = (size_t)rrow * N_PIX + p;
                    bf16 h0, l0, h1, l1;
                    fsplit(v0, h0, l0); fsplit(v1, h1, l1);
                    *(uint32_t*)(Yhi + z * ys + o) = pack2(h0, h1);
                    *(uint32_t*)(Ylo + z * ys + o) = pack2(l0, l1);
                }
                s_th += __shfl_xor_sync(0xffffffffu, s_th, 1);
                s_th += __shfl_xor_sync(0xffffffffu, s_th, 2);
                if (tig == 0)
                    rs[((size_t)z * 512 + rrow) * 512 + blockIdx.x * 4 + wn] = s_th;
            }
        return;
    }

#pragma unroll
    for (int mt = 0; mt < MT; ++mt) {
#pragma unroll
        for (int h2 = 0; h2 < 2; ++h2) {
            int rrow = o0 + wm * WM + mt * 16 + g + h2 * 8;
            float bb = (MODE == 3) ? __ldg(&bias[rrow]) : 0.f;
#pragma unroll
            for (int nt = 0; nt < 4; ++nt) {
                int p = pblk + wn * 32 + nt * 8 + tig * 2;
                float v0 = acc[mt][nt][h2 * 2 + 0] + bb;
                float v1 = acc[mt][nt][h2 * 2 + 1] + bb;
                size_t o = (size_t)rrow * N_PIX + p;
                if (MODE == 0 || MODE == 3) {
                    *(float2*)(Yf + z * ys + o) = make_float2(v0, v1);
                } else {
                    if (MODE == 2) { v0 = gelu_exact(v0); v1 = gelu_exact(v1); }
                    bf16 h0, l0, h1, l1;
                    fsplit(v0, h0, l0); fsplit(v1, h1, l1);
                    *(uint32_t*)(Yhi + z * ys + o) = pack2(h0, h1);
                    *(uint32_t*)(Ylo + z * ys + o) = pack2(l0, l1);
                }
            }
        }
    }
}

// ---------------- reduce exp-row partial sums -> 1/S per k-row ----------------
__global__ void __launch_bounds__(256) k_sumred(const float* __restrict__ rs,
                                                float* __restrict__ sinv)
{
    int row = blockIdx.x * 8 + (threadIdx.x >> 5);   // 512 blocks x 8 warps = 4096 rows
    int lane = threadIdx.x & 31;
    const float* p = rs + (size_t)row * 512;
    float s = 0.f;
#pragma unroll
    for (int i = 0; i < 16; ++i) s += p[lane + i * 32];
#pragma unroll
    for (int o = 16; o; o >>= 1) s += __shfl_xor_sync(0xffffffffu, s, o);
    if (lane == 0) sinv[row] = 1.0f / s;
}

// ---------------- context partials (tensor, pipelined): P[bh,s][e][d] ----------------
__global__ void __launch_bounds__(256, 2) k_ctx_t(
    const bf16* __restrict__ khi, const bf16* __restrict__ klo,
    const bf16* __restrict__ vhi, const bf16* __restrict__ vlo,
    float* __restrict__ part)
{
    constexpr int P = 72;
    constexpr uint32_t ASZ = 64 * P * 2;
    extern __shared__ __align__(16) bf16 smp[];

    int t = threadIdx.x, warp = t >> 5, lane = t & 31;
    int wm = warp & 1, wn = warp >> 1;
    int g = lane >> 2, tig = lane & 3;
    int bh = blockIdx.x >> 3, s = blockIdx.x & 7;
    size_t cb = (size_t)bh * 64 * N_PIX + (size_t)s * 2048;

    const uint32_t base = s2u(smp);
#define CARR(st, a) (base + ((uint32_t)(st) * 4 + (a)) * ASZ)

#define CTX_LOAD(st, itv) do {                                                \
    for (int i = t; i < 512; i += 256) {                                      \
        int row = i >> 3, c8 = (i & 7) * 8;                                   \
        size_t src = cb + (size_t)row * N_PIX + (itv) * 64 + c8;              \
        uint32_t d_ = (uint32_t)(row * P + c8) * 2;                           \
        cpa16(CARR(st, 0) + d_, khi + src);                                   \
        cpa16(CARR(st, 1) + d_, klo + src);                                   \
        cpa16(CARR(st, 2) + d_, vhi + src);                                   \
        cpa16(CARR(st, 3) + d_, vlo + src);                                   \
    }                                                                         \
    cp_commit();                                                              \
} while (0)

    float acc[2][2][4];
#pragma unroll
    for (int m = 0; m < 2; ++m)
#pragma unroll
        for (int n = 0; n < 2; ++n)
#pragma unroll
            for (int r = 0; r < 4; ++r) acc[m][n][r] = 0.f;

    const int l15 = lane & 15, hi8 = (lane >> 4) * 8;
    const int bg = lane >> 3, bl = lane & 7;
    const int brow = (bg >> 1) * 8 + bl;
    const int bcol = (bg & 1) * 8;

    CTX_LOAD(0, 0);
    for (int it = 0; it < 32; ++it) {
        int st = it & 1;
        if (it + 1 < 32) { CTX_LOAD(st ^ 1, it + 1); cp_wait<1>(); }
        else cp_wait<0>();
        __syncthreads();

        const uint32_t kB0 = CARR(st, 0), kB1 = CARR(st, 1);
        const uint32_t vB0 = CARR(st, 2), vB1 = CARR(st, 3);

#pragma unroll
        for (int ks = 0; ks < 64; ks += 16) {
            uint32_t bh_[2][2], bl_[2][2], r[4];
            uint32_t boff = (uint32_t)((wn * 16 + brow) * P + ks + bcol) * 2;
            ldsm4(r, kB0 + boff);
            bh_[0][0] = r[0]; bh_[0][1] = r[1]; bh_[1][0] = r[2]; bh_[1][1] = r[3];
            ldsm4(r, kB1 + boff);
            bl_[0][0] = r[0]; bl_[0][1] = r[1]; bl_[1][0] = r[2]; bl_[1][1] = r[3];
#pragma unroll
            for (int mt = 0; mt < 2; ++mt) {
                uint32_t ah[4], al[4];
                uint32_t aoff = (uint32_t)((wm * 32 + mt * 16 + l15) * P + ks + hi8) * 2;
                ldsm4(ah, vB0 + aoff);
                ldsm4(al, vB1 + aoff);
#pragma unroll
                for (int nt = 0; nt < 2; ++nt) {
                    mma_bf16(acc[mt][nt], ah, bh_[nt]);
                    mma_bf16(acc[mt][nt], al, bh_[nt]);
                    mma_bf16(acc[mt][nt], ah, bl_[nt]);
                }
            }
        }
        __syncthreads();
    }
#undef CTX_LOAD
#undef CARR

    size_t ob = (size_t)blockIdx.x * 4096;
#pragma unroll
    for (int mt = 0; mt < 2; ++mt)
#pragma unroll
        for (int h2 = 0; h2 < 2; ++h2) {
            int e = wm * 32 + mt * 16 + g + h2 * 8;
#pragma unroll
            for (int nt = 0; nt < 2; ++nt) {
                int d = wn * 16 + nt * 8 + tig * 2;
                *(float2*)&part[ob + (size_t)e * 64 + d] =
                    make_float2(acc[mt][nt][h2 * 2], acc[mt][nt][h2 * 2 + 1]);
            }
        }
}

// ---------------- reduce partials; normalize by 1/S[d]; emit ctx^T hi/lo ----------------
__global__ void k_ctx_reduce(const float* __restrict__ part, const float* __restrict__ sinv,
                             bf16* __restrict__ chi, bf16* __restrict__ clo)
{
    int i = blockIdx.x * 256 + threadIdx.x;
    int bh = i >> 12, ed = i & 4095;
    int d = ed & 63;
    float s = 0.f;
#pragma unroll
    for (int ss = 0; ss < 8; ++ss)
        s += part[((size_t)bh * 8 + ss) * 4096 + ed];
    s *= sinv[(bh >> 3) * 512 + (bh & 7) * 64 + d];
    bf16 h, l; fsplit(s, h, l);
    chi[i] = h; clo[i] = l;
}

// ---------------- launch ----------------
extern "C" void kernel_launch(void* const* d_in, const int* in_sizes, int n_in,
                              void* d_out, int out_size)
{
    const float* fmap  = (const float*)d_in[0];
    const float* w_q   = (const float*)d_in[1];
    const float* w_dw  = (const float*)d_in[2];
    const float* w_pw  = (const float*)d_in[3];
    const float* w_out = (const float*)d_in[4];
    const float* b_out = (const float*)d_in[5];
    float* out = (float*)d_out;

    float *part, *rs, *sinv;
    bf16 *fhi, *flo, *dwhi, *dwlo, *qhi, *qlo, *khi, *klo, *vhi, *vlo;
    bf16 *avhi, *avlo, *chi, *clo, *wqh, *wql, *wph, *wpl, *woh, *wol;
    cudaGetSymbolAddress((void**)&part, g_part);
    cudaGetSymbolAddress((void**)&rs,   g_rs);
    cudaGetSymbolAddress((void**)&sinv, g_sinv);
    cudaGetSymbolAddress((void**)&fhi,  g_fhi);   cudaGetSymbolAddress((void**)&flo,  g_flo);
    cudaGetSymbolAddress((void**)&dwhi, g_dwhi);  cudaGetSymbolAddress((void**)&dwlo, g_dwlo);
    cudaGetSymbolAddress((void**)&qhi,  g_qhi);   cudaGetSymbolAddress((void**)&qlo,  g_qlo);
    cudaGetSymbolAddress((void**)&khi,  g_khi);   cudaGetSymbolAddress((void**)&klo,  g_klo);
    cudaGetSymbolAddress((void**)&vhi,  g_vhi);   cudaGetSymbolAddress((void**)&vlo,  g_vlo);
    cudaGetSymbolAddress((void**)&avhi, g_avhi);  cudaGetSymbolAddress((void**)&avlo, g_avlo);
    cudaGetSymbolAddress((void**)&chi,  g_ctxhi); cudaGetSymbolAddress((void**)&clo,  g_ctxlo);
    cudaGetSymbolAddress((void**)&wqh,  g_wqhi);  cudaGetSymbolAddress((void**)&wql,  g_wqlo);
    cudaGetSymbolAddress((void**)&wph,  g_wpwhi); cudaGetSymbolAddress((void**)&wpl,  g_wpwlo);
    cudaGetSymbolAddress((void**)&woh,  g_wohi);  cudaGetSymbolAddress((void**)&wol,  g_wolo);

    const int SM128 = 8 * (40 * 128 + 4352);   // 75776 B
    const int SM64  = 8 * (40 * 64 + 4352);    // 55296 B
    const int SMCTX = 2 * 4 * 64 * 72 * 2;     // 73728 B
    cudaFuncSetAttribute(k_mma_gemm<128,4>, cudaFuncAttributeMaxDynamicSharedMemorySize, SM128);
    cudaFuncSetAttribute(k_mma_gemm<128,5>, cudaFuncAttributeMaxDynamicSharedMemorySize, SM128);
    cudaFuncSetAttribute(k_mma_gemm<128,1>, cudaFuncAttributeMaxDynamicSharedMemorySize, SM128);
    cudaFuncSetAttribute(k_mma_gemm<128,3>, cudaFuncAttributeMaxDynamicSharedMemorySize, SM128);
    cudaFuncSetAttribute(k_mma_gemm<64,2>,  cudaFuncAttributeMaxDynamicSharedMemorySize, SM64);
    cudaFuncSetAttribute(k_ctx_t,           cudaFuncAttributeMaxDynamicSharedMemorySize, SMCTX);

    // 0) weight splits
    k_cvt<<<512, 256>>>(w_q, wqh, wql, 512 * 256);
    k_cvt<<<1024, 256>>>(w_pw, wph, wpl, 1024 * 256);
    k_cvt<<<512, 256>>>(w_out, woh, wol, 256 * 512);

    // 1) depthwise 3x3 + fmap/dw hi-lo planes
    k_dwconv<<<dim3(16, BATCH * 256), 256>>>(fmap, w_dw);

    // 2) q = softmax_d(w_q @ fmap) * 1/8  (fused, hl out)
    k_mma_gemm<128, 4><<<dim3(128, 4, 8), 256, SM128>>>(
        wqh, wql, fhi, flo, nullptr, nullptr, nullptr, qhi, qlo,
        256, 0, 256LL * N_PIX, 512LL * N_PIX);

    // 3a) exp(k) = exp(w_pw[0:512] @ dw)  (hl out + partial row sums)
    k_mma_gemm<128, 5><<<dim3(128, 4, 8), 256, SM128>>>(
        wph, wpl, dwhi, dwlo, nullptr, rs, nullptr, khi, klo,
        256, 0, 256LL * N_PIX, 512LL * N_PIX);

    // 3b) v = w_pw[512:1024] @ dw  (hl out)
    k_mma_gemm<128, 1><<<dim3(128, 4, 8), 256, SM128>>>(
        wph + 512 * 256, wpl + 512 * 256, dwhi, dwlo, nullptr, nullptr,
        nullptr, vhi, vlo, 256, 0, 256LL * N_PIX, 512LL * N_PIX);

    // 4) softmax-N normalizer: 1/S per k-row
    k_sumred<<<512, 256>>>(rs, sinv);

    // 5) context: pipelined tensor split-K partials + normalize-reduce
    k_ctx_t<<<512, 256, SMCTX>>>(khi, klo, vhi, vlo, part);
    k_ctx_reduce<<<1024, 256>>>(part, sinv, chi, clo);

    // 6) av = gelu(ctx^T @ q)  batched over 64 (b,h)  (hl out)
    k_mma_gemm<64, 2><<<dim3(128, 1, 64), 256, SM64>>>(
        chi, clo, qhi, qlo, nullptr, nullptr, nullptr, avhi, avlo,
        64, 4096LL, 64LL * N_PIX, 64LL * N_PIX);

    // 7) out = w_out @ av + b_out  (fp32 + bias)
    k_mma_gemm<128, 3><<<dim3(128, 2, 8), 256, SM128>>>(
        woh, wol, avhi, avlo, b_out, nullptr, out, nullptr, nullptr,
        512, 0, 512LL * N_PIX, 256LL * N_PIX);
}

// round 13
// speedup vs baseline: 1.5065x; 1.0101x over previous
#include <cuda_runtime.h>
#include <cuda_bf16.h>
#include <math.h>
#include <stdint.h>

#define N_PIX  16384
#define BATCH  8

typedef __nv_bfloat16 bf16;

// ---------------- scratch (static device globals; no allocation) ----------------
__device__ __align__(16) float g_part[64 * 8 * 64 * 64];
__device__ __align__(16) float g_rs  [4096 * 512];     // per-(k-row, 32px-group) exp sums
__device__ __align__(16) float g_sinv[4096];           // 1 / rowsum

__device__ __align__(16) bf16 g_fhi [(size_t)BATCH * 256 * N_PIX];
__device__ __align__(16) bf16 g_flo [(size_t)BATCH * 256 * N_PIX];
__device__ __align__(16) bf16 g_dwhi[(size_t)BATCH * 256 * N_PIX];
__device__ __align__(16) bf16 g_dwlo[(size_t)BATCH * 256 * N_PIX];
__device__ __align__(16) bf16 g_qhi [(size_t)BATCH * 512 * N_PIX];
__device__ __align__(16) bf16 g_qlo [(size_t)BATCH * 512 * N_PIX];
__device__ __align__(16) bf16 g_khi [(size_t)BATCH * 512 * N_PIX];   // exp(k) planes
__device__ __align__(16) bf16 g_klo [(size_t)BATCH * 512 * N_PIX];
__device__ __align__(16) bf16 g_vhi [(size_t)BATCH * 512 * N_PIX];
__device__ __align__(16) bf16 g_vlo [(size_t)BATCH * 512 * N_PIX];
__device__ __align__(16) bf16 g_avhi[(size_t)BATCH * 512 * N_PIX];
__device__ __align__(16) bf16 g_avlo[(size_t)BATCH * 512 * N_PIX];
__device__ __align__(16) bf16 g_ctxhi[64 * 64 * 64];
__device__ __align__(16) bf16 g_ctxlo[64 * 64 * 64];
__device__ __align__(16) bf16 g_wqhi [512 * 256],  g_wqlo [512 * 256];
__device__ __align__(16) bf16 g_wpwhi[1024 * 256], g_wpwlo[1024 * 256];
__device__ __align__(16) bf16 g_wohi [256 * 512],  g_wolo [256 * 512];

// ---------------- helpers ----------------
__device__ __forceinline__ float gelu_exact(float x) { return x * normcdff(x); }
__device__ __forceinline__ void fsplit(float x, bf16& h, bf16& l) {
    h = __float2bfloat16_rn(x);
    l = __float2bfloat16_rn(x - __bfloat162float(h));
}
__device__ __forceinline__ uint32_t pack2(bf16 a, bf16 b) {
    __nv_bfloat162 t; t.x = a; t.y = b;
    return *reinterpret_cast<uint32_t*>(&t);
}
__device__ __forceinline__ void mma_bf16(float d[4], const uint32_t a[4], const uint32_t b[2]) {
    asm volatile("mma.sync.aligned.m16n8k16.row.col.f32.bf16.bf16.f32 "
                 "{%0,%1,%2,%3}, {%4,%5,%6,%7}, {%8,%9}, {%0,%1,%2,%3};"
                 : "+f"(d[0]), "+f"(d[1]), "+f"(d[2]), "+f"(d[3])
                 : "r"(a[0]), "r"(a[1]), "r"(a[2]), "r"(a[3]), "r"(b[0]), "r"(b[1]));
}
__device__ __forceinline__ void ldsm4(uint32_t r[4], uint32_t addr) {
    asm volatile("ldmatrix.sync.aligned.m8n8.x4.shared.b16 {%0,%1,%2,%3}, [%4];"
                 : "=r"(r[0]), "=r"(r[1]), "=r"(r[2]), "=r"(r[3]) : "r"(addr));
}
__device__ __forceinline__ void ldsm4t(uint32_t r[4], uint32_t addr) {
    asm volatile("ldmatrix.sync.aligned.m8n8.x4.trans.shared.b16 {%0,%1,%2,%3}, [%4];"
                 : "=r"(r[0]), "=r"(r[1]), "=r"(r[2]), "=r"(r[3]) : "r"(addr));
}
__device__ __forceinline__ uint32_t s2u(const void* p) {
    return (uint32_t)__cvta_generic_to_shared(p);
}
__device__ __forceinline__ void cpa16(uint32_t dst, const void* src) {
    asm volatile("cp.async.cg.shared.global [%0], [%1], 16;" :: "r"(dst), "l"(src));
}
__device__ __forceinline__ void cp_commit() {
    asm volatile("cp.async.commit_group;");
}
template <int N>
__device__ __forceinline__ void cp_wait() {
    asm volatile("cp.async.wait_group %0;" :: "n"(N));
}

// ---------------- weight convert: fp32 -> bf16 hi/lo ----------------
__global__ void k_cvt(const float* __restrict__ x, bf16* __restrict__ hi,
                      bf16* __restrict__ lo, int n)
{
    int i = blockIdx.x * 256 + threadIdx.x;
    if (i < n) { bf16 h, l; fsplit(x[i], h, l); hi[i] = h; lo[i] = l; }
}

// ---------------- depthwise 3x3 (pad 1); 4 px/thread; emit dw & fmap hi/lo ----------------
__global__ void __launch_bounds__(256) k_dwconv(const float* __restrict__ in,
                                                const float* __restrict__ wdw)
{
    int plane = blockIdx.y;              // b*256 + c
    int c = plane & 255;
    const float* ip = in + (size_t)plane * N_PIX;

    float w[9];
#pragma unroll
    for (int k = 0; k < 9; ++k) w[k] = __ldg(wdw + c * 9 + k);

    int p4 = (blockIdx.x * 256 + threadIdx.x) * 4;
    int y = p4 >> 7, x0 = p4 & 127;

    float L[3][6];
#pragma unroll
    for (int r = 0; r < 3; ++r) {
        int yy = y + r - 1;
        if (yy < 0 || yy > 127) {
#pragma unroll
            for (int j = 0; j < 6; ++j) L[r][j] = 0.f;
        } else {
            const float* rp = ip + yy * 128 + x0;
            float4 f = *(const float4*)rp;
            L[r][1] = f.x; L[r][2] = f.y; L[r][3] = f.z; L[r][4] = f.w;
            L[r][0] = (x0 > 0)   ? __ldg(rp - 1) : 0.f;
            L[r][5] = (x0 < 124) ? __ldg(rp + 4) : 0.f;
        }
    }

    bf16 h[4], l[4];
    size_t o = (size_t)plane * N_PIX + p4;
#pragma unroll
    for (int i = 0; i < 4; ++i) {
        float s = 0.f;
#pragma unroll
        for (int r = 0; r < 3; ++r)
#pragma unroll
            for (int dx = 0; dx < 3; ++dx)
                s += L[r][i + dx] * w[r * 3 + dx];
        fsplit(s, h[i], l[i]);
    }
    *(uint2*)(g_dwhi + o) = make_uint2(pack2(h[0], h[1]), pack2(h[2], h[3]));
    *(uint2*)(g_dwlo + o) = make_uint2(pack2(l[0], l[1]), pack2(l[2], l[3]));
#pragma unroll
    for (int i = 0; i < 4; ++i) fsplit(L[1][1 + i], h[i], l[i]);
    *(uint2*)(g_fhi + o) = make_uint2(pack2(h[0], h[1]), pack2(h[2], h[3]));
    *(uint2*)(g_flo + o) = make_uint2(pack2(l[0], l[1]), pack2(l[2], l[3]));
}

// ---------------- split-bf16 tensor-core GEMM, 3-stage cp.async pipeline ----------------
// Y[o,p] = sum_c A[o,c] * X[c,p].  A hi/lo row-major [O,C]; X hi/lo [C,N_PIX].
// Grid: (128 pixel-blocks, O/BM, z) — pixel-major.
// MODE: 2 gelu+hl, 3 bias+fp32, 4 softmax-d(64)+scale+hl,
//       6 fused kv: rows<512 -> exp+hl(Yhi/Ylo)+rowsum partials; rows>=512 -> hl(Y2hi/Y2lo).
template <int BM, int MODE>
__global__ void __launch_bounds__(256, 2) k_mma_gemm(
    const bf16* __restrict__ Ahi, const bf16* __restrict__ Alo,
    const bf16* __restrict__ Bhi, const bf16* __restrict__ Blo,
    const float* __restrict__ bias, float* __restrict__ rs,
    float* __restrict__ Yf, bf16* __restrict__ Yhi, bf16* __restrict__ Ylo,
    bf16* __restrict__ Y2hi, bf16* __restrict__ Y2lo,
    int C, long long as_, long long xs, long long ys)
{
    constexpr int BN = 128, BK = 32, AP = 40, BP = 136;
    constexpr int WM = BM / 2, MT = WM / 16;
    constexpr uint32_t APl = BM * AP * 2;   // bytes per A plane per stage
    constexpr uint32_t BPl = BK * BP * 2;

    extern __shared__ __align__(16) bf16 smp[];

    const int t = threadIdx.x, warp = t >> 5, lane = t & 31;
    const int wm = warp & 1, wn = warp >> 1;
    const int g = lane >> 2, tig = lane & 3;
    const int pblk = blockIdx.x * BN, o0 = blockIdx.y * BM;
    const long long z = blockIdx.z;
    const bf16* AH = Ahi + z * as_;
    const bf16* AL = Alo + z * as_;
    const bf16* XH = Bhi + z * xs;
    const bf16* XL = Blo + z * xs;

    const uint32_t Abase = s2u(smp);
    const uint32_t Bbase = Abase + 6 * APl;     // 3 stages x 2 planes

#define LOAD_STAGE(st, c0v) do {                                              \
    uint32_t aD = Abase + (uint32_t)(st) * 2 * APl;                           \
    uint32_t bD = Bbase + (uint32_t)(st) * 2 * BPl;                           \
    for (int i = t; i < BM * 4; i += 256) {                                   \
        int m_ = i >> 2, kq = (i & 3) * 8;                                    \
        size_t src = (size_t)(o0 + m_) * C + (c0v) + kq;                      \
        uint32_t d_ = (uint32_t)(m_ * AP + kq) * 2;                           \
        cpa16(aD + d_, AH + src);                                             \
        cpa16(aD + APl + d_, AL + src);                                       \
    }                                                                         \
    for (int i = t; i < 512; i += 256) {                                      \
        int cc = i >> 4, pq = (i & 15) * 8;                                   \
        size_t src = (size_t)((c0v) + cc) * N_PIX + pblk + pq;                \
        uint32_t d_ = (uint32_t)(cc * BP + pq) * 2;                           \
        cpa16(bD + d_, XH + src);                                             \
        cpa16(bD + BPl + d_, XL + src);                                       \
    }                                                                         \
    cp_commit();                                                              \
} while (0)

    float acc[MT][4][4];
#pragma unroll
    for (int m = 0; m < MT; ++m)
#pragma unroll
        for (int n = 0; n < 4; ++n)
#pragma unroll
            for (int r = 0; r < 4; ++r) acc[m][n][r] = 0.f;

    const int l15 = lane & 15;
    const int hi8 = (lane >> 4) * 8;

    const int T = C >> 5;
    LOAD_STAGE(0, 0);
    if (T > 1) LOAD_STAGE(1, BK);

    for (int it = 0; it < T; ++it) {
        const int st = it % 3;
        if (it == T - 1) cp_wait<0>(); else cp_wait<1>();
        __syncthreads();
        if (it + 2 < T) LOAD_STAGE((it + 2) % 3, (it + 2) * BK);

        const uint32_t a0 = Abase + (uint32_t)st * 2 * APl;
        const uint32_t a1 = a0 + APl;
        const uint32_t b0 = Bbase + (uint32_t)st * 2 * BPl;
        const uint32_t b1 = b0 + BPl;

#pragma unroll
        for (int ks = 0; ks < BK; ks += 16) {
            uint32_t bh_[4][2], bl_[4][2], r[4];
#pragma unroll
            for (int nn = 0; nn < 2; ++nn) {
                uint32_t off = (uint32_t)((ks + l15) * BP + wn * 32 + nn * 16 + hi8) * 2;
                ldsm4t(r, b0 + off);
                bh_[nn*2][0] = r[0]; bh_[nn*2][1] = r[1];
                bh_[nn*2+1][0] = r[2]; bh_[nn*2+1][1] = r[3];
                ldsm4t(r, b1 + off);
                bl_[nn*2][0] = r[0]; bl_[nn*2][1] = r[1];
                bl_[nn*2+1][0] = r[2]; bl_[nn*2+1][1] = r[3];
            }
#pragma unroll
            for (int mt = 0; mt < MT; ++mt) {
                uint32_t ah[4], al[4];
                uint32_t off = (uint32_t)((wm * WM + mt * 16 + l15) * AP + ks + hi8) * 2;
                ldsm4(ah, a0 + off);
                ldsm4(al, a1 + off);
#pragma unroll
                for (int nt = 0; nt < 4; ++nt) {
                    mma_bf16(acc[mt][nt], ah, bh_[nt]);
                    mma_bf16(acc[mt][nt], al, bh_[nt]);
                    mma_bf16(acc[mt][nt], ah, bl_[nt]);
                }
            }
        }
    }
#undef LOAD_STAGE

    if (MODE == 4) {
        // softmax over the 64 rows of this warp-half (one head), per pixel column; *1/8
        float sc[8];
#pragma unroll
        for (int nt = 0; nt < 4; ++nt)
#pragma unroll
            for (int c = 0; c < 2; ++c) {
                float m = -3.4e38f;
#pragma unroll
                for (int mt = 0; mt < MT; ++mt) {
                    m = fmaxf(m, acc[mt][nt][c]);
                    m = fmaxf(m, acc[mt][nt][2 + c]);
                }
                m = fmaxf(m, __shfl_xor_sync(0xffffffffu, m, 4));
                m = fmaxf(m, __shfl_xor_sync(0xffffffffu, m, 8));
                m = fmaxf(m, __shfl_xor_sync(0xffffffffu, m, 16));
                float s = 0.f;
#pragma unroll
                for (int mt = 0; mt < MT; ++mt) {
                    float e0 = expf(acc[mt][nt][c] - m);
                    float e1 = expf(acc[mt][nt][2 + c] - m);
                    acc[mt][nt][c] = e0; acc[mt][nt][2 + c] = e1;
                    s += e0 + e1;
                }
                s += __shfl_xor_sync(0xffffffffu, s, 4);
                s += __shfl_xor_sync(0xffffffffu, s, 8);
                s += __shfl_xor_sync(0xffffffffu, s, 16);
                sc[nt * 2 + c] = 0.125f / s;
            }
#pragma unroll
        for (int mt = 0; mt < MT; ++mt)
#pragma unroll
            for (int h2 = 0; h2 < 2; ++h2) {
                int rrow = o0 + wm * WM + mt * 16 + g + h2 * 8;
#pragma unroll
                for (int nt = 0; nt < 4; ++nt) {
                    int p = pblk + wn * 32 + nt * 8 + tig * 2;
                    float v0 = acc[mt][nt][h2 * 2 + 0] * sc[nt * 2 + 0];
                    float v1 = acc[mt][nt][h2 * 2 + 1] * sc[nt * 2 + 1];
                    size_t o = (size_t)rrow * N_PIX + p;
                    bf16 h0, l0, h1, l1;
                    fsplit(v0, h0, l0); fsplit(v1, h1, l1);
                    *(uint32_t*)(Yhi + z * ys + o) = pack2(h0, h1);
                    *(uint32_t*)(Ylo + z * ys + o) = pack2(l0, l1);
                }
            }
        return;
    }

    if (MODE == 6) {
        if (o0 < 512) {
            // k rows: exp(acc); hl planes; per-(row, 32px) partial sums
#pragma unroll
            for (int mt = 0; mt < MT; ++mt)
#pragma unroll
                for (int h2 = 0; h2 < 2; ++h2) {
                    int rrow = o0 + wm * WM + mt * 16 + g + h2 * 8;
                    float s_th = 0.f;
#pragma unroll
                    for (int nt = 0; nt < 4; ++nt) {
                        int p = pblk + wn * 32 + nt * 8 + tig * 2;
                        float v0 = expf(acc[mt][nt][h2 * 2 + 0]);
                        float v1 = expf(acc[mt][nt][h2 * 2 + 1]);
                        s_th += v0 + v1;
                        size_t o = (size_t)rrow * N_PIX + p;
                        bf16 h0, l0, h1, l1;
                        fsplit(v0, h0, l0); fsplit(v1, h1, l1);
                        *(uint32_t*)(Yhi + z * ys + o) = pack2(h0, h1);
                        *(uint32_t*)(Ylo + z * ys + o) = pack2(l0, l1);
                    }
                    s_th += __shfl_xor_sync(0xffffffffu, s_th, 1);
                    s_th += __shfl_xor_sync(0xffffffffu, s_th, 2);
                    if (tig == 0)
                        rs[((size_t)z * 512 + rrow) * 512 + blockIdx.x * 4 + wn] = s_th;
                }
        } else {
            // v rows: plain hl out
#pragma unroll
            for (int mt = 0; mt < MT; ++mt)
#pragma unroll
                for (int h2 = 0; h2 < 2; ++h2) {
                    int rrow = o0 - 512 + wm * WM + mt * 16 + g + h2 * 8;
#pragma unroll
                    for (int nt = 0; nt < 4; ++nt) {
                        int p = pblk + wn * 32 + nt * 8 + tig * 2;
                        float v0 = acc[mt][nt][h2 * 2 + 0];
                        float v1 = acc[mt][nt][h2 * 2 + 1];
                        size_t o = (size_t)rrow * N_PIX + p;
                        bf16 h0, l0, h1, l1;
                        fsplit(v0, h0, l0); fsplit(v1, h1, l1);
                        *(uint32_t*)(Y2hi + z * ys + o) = pack2(h0, h1);
                        *(uint32_t*)(Y2lo + z * ys + o) = pack2(l0, l1);
                    }
                }
        }
        return;
    }

#pragma unroll
    for (int mt = 0; mt < MT; ++mt) {
#pragma unroll
        for (int h2 = 0; h2 < 2; ++h2) {
            int rrow = o0 + wm * WM + mt * 16 + g + h2 * 8;
            float bb = (MODE == 3) ? __ldg(&bias[rrow]) : 0.f;
#pragma unroll
            for (int nt = 0; nt < 4; ++nt) {
                int p = pblk + wn * 32 + nt * 8 + tig * 2;
                float v0 = acc[mt][nt][h2 * 2 + 0] + bb;
                float v1 = acc[mt][nt][h2 * 2 + 1] + bb;
                size_t o = (size_t)rrow * N_PIX + p;
                if (MODE == 3) {
                    *(float2*)(Yf + z * ys + o) = make_float2(v0, v1);
                } else {
                    if (MODE == 2) { v0 = gelu_exact(v0); v1 = gelu_exact(v1); }
                    bf16 h0, l0, h1, l1;
                    fsplit(v0, h0, l0); fsplit(v1, h1, l1);
                    *(uint32_t*)(Yhi + z * ys + o) = pack2(h0, h1);
                    *(uint32_t*)(Ylo + z * ys + o) = pack2(l0, l1);
                }
            }
        }
    }
}

// ---------------- reduce exp-row partial sums -> 1/S per k-row ----------------
__global__ void __launch_bounds__(256) k_sumred(const float* __restrict__ rs,
                                                float* __restrict__ sinv)
{
    int row = blockIdx.x * 8 + (threadIdx.x >> 5);   // 512 blocks x 8 warps = 4096 rows
    int lane = threadIdx.x & 31;
    const float* p = rs + (size_t)row * 512;
    float s = 0.f;
#pragma unroll
    for (int i = 0; i < 16; ++i) s += p[lane + i * 32];
#pragma unroll
    for (int o = 16; o; o >>= 1) s += __shfl_xor_sync(0xffffffffu, s, o);
    if (lane == 0) sinv[row] = 1.0f / s;
}

// ---------------- context partials (tensor, 3-stage pipelined): P[bh,s][e][d] ----------------
__global__ void __launch_bounds__(256, 2) k_ctx_t(
    const bf16* __restrict__ khi, const bf16* __restrict__ klo,
    const bf16* __restrict__ vhi, const bf16* __restrict__ vlo,
    float* __restrict__ part)
{
    constexpr int P = 72;
    constexpr uint32_t ASZ = 64 * P * 2;
    extern __shared__ __align__(16) bf16 smp[];

    int t = threadIdx.x, warp = t >> 5, lane = t & 31;
    int wm = warp & 1, wn = warp >> 1;
    int g = lane >> 2, tig = lane & 3;
    int bh = blockIdx.x >> 3, s = blockIdx.x & 7;
    size_t cb = (size_t)bh * 64 * N_PIX + (size_t)s * 2048;

    const uint32_t base = s2u(smp);
#define CARR(st, a) (base + ((uint32_t)(st) * 4 + (a)) * ASZ)

#define CTX_LOAD(st, itv) do {                                                \
    for (int i = t; i < 512; i += 256) {                                      \
        int row = i >> 3, c8 = (i & 7) * 8;                                   \
        size_t src = cb + (size_t)row * N_PIX + (itv) * 64 + c8;              \
        uint32_t d_ = (uint32_t)(row * P + c8) * 2;                           \
        cpa16(CARR(st, 0) + d_, khi + src);                                   \
        cpa16(CARR(st, 1) + d_, klo + src);                                   \
        cpa16(CARR(st, 2) + d_, vhi + src);                                   \
        cpa16(CARR(st, 3) + d_, vlo + src);                                   \
    }                                                                         \
    cp_commit();                                                              \
} while (0)

    float acc[2][2][4];
#pragma unroll
    for (int m = 0; m < 2; ++m)
#pragma unroll
        for (int n = 0; n < 2; ++n)
#pragma unroll
            for (int r = 0; r < 4; ++r) acc[m][n][r] = 0.f;

    const int l15 = lane & 15, hi8 = (lane >> 4) * 8;
    const int bg = lane >> 3, bl = lane & 7;
    const int brow = (bg >> 1) * 8 + bl;
    const int bcol = (bg & 1) * 8;

    CTX_LOAD(0, 0);
    CTX_LOAD(1, 1);
    for (int it = 0; it < 32; ++it) {
        int st = it % 3;
        if (it == 31) cp_wait<0>(); else cp_wait<1>();
        __syncthreads();
        if (it + 2 < 32) CTX_LOAD((it + 2) % 3, it + 2);

        const uint32_t kB0 = CARR(st, 0), kB1 = CARR(st, 1);
        const uint32_t vB0 = CARR(st, 2), vB1 = CARR(st, 3);

#pragma unroll
        for (int ks = 0; ks < 64; ks += 16) {
            uint32_t bh_[2][2], bl_[2][2], r[4];
            uint32_t boff = (uint32_t)((wn * 16 + brow) * P + ks + bcol) * 2;
            ldsm4(r, kB0 + boff);
            bh_[0][0] = r[0]; bh_[0][1] = r[1]; bh_[1][0] = r[2]; bh_[1][1] = r[3];
            ldsm4(r, kB1 + boff);
            bl_[0][0] = r[0]; bl_[0][1] = r[1]; bl_[1][0] = r[2]; bl_[1][1] = r[3];
#pragma unroll
            for (int mt = 0; mt < 2; ++mt) {
                uint32_t ah[4], al[4];
                uint32_t aoff = (uint32_t)((wm * 32 + mt * 16 + l15) * P + ks + hi8) * 2;
                ldsm4(ah, vB0 + aoff);
                ldsm4(al, vB1 + aoff);
#pragma unroll
                for (int nt = 0; nt < 2; ++nt) {
                    mma_bf16(acc[mt][nt], ah, bh_[nt]);
                    mma_bf16(acc[mt][nt], al, bh_[nt]);
                    mma_bf16(acc[mt][nt], ah, bl_[nt]);
                }
            }
        }
    }
#undef CTX_LOAD
#undef CARR

    size_t ob = (size_t)blockIdx.x * 4096;
#pragma unroll
    for (int mt = 0; mt < 2; ++mt)
#pragma unroll
        for (int h2 = 0; h2 < 2; ++h2) {
            int e = wm * 32 + mt * 16 + g + h2 * 8;
#pragma unroll
            for (int nt = 0; nt < 2; ++nt) {
                int d = wn * 16 + nt * 8 + tig * 2;
                *(float2*)&part[ob + (size_t)e * 64 + d] =
                    make_float2(acc[mt][nt][h2 * 2], acc[mt][nt][h2 * 2 + 1]);
            }
        }
}

// ---------------- reduce partials; normalize by 1/S[d]; emit ctx^T hi/lo ----------------
__global__ void k_ctx_reduce(const float* __restrict__ part, const float* __restrict__ sinv,
                             bf16* __restrict__ chi, bf16* __restrict__ clo)
{
    int i = blockIdx.x * 256 + threadIdx.x;
    int bh = i >> 12, ed = i & 4095;
    int d = ed & 63;
    float s = 0.f;
#pragma unroll
    for (int ss = 0; ss < 8; ++ss)
        s += part[((size_t)bh * 8 + ss) * 4096 + ed];
    s *= sinv[(bh >> 3) * 512 + (bh & 7) * 64 + d];
    bf16 h, l; fsplit(s, h, l);
    chi[i] = h; clo[i] = l;
}

// ---------------- launch ----------------
extern "C" void kernel_launch(void* const* d_in, const int* in_sizes, int n_in,
                              void* d_out, int out_size)
{
    const float* fmap  = (const float*)d_in[0];
    const float* w_q   = (const float*)d_in[1];
    const float* w_dw  = (const float*)d_in[2];
    const float* w_pw  = (const float*)d_in[3];
    const float* w_out = (const float*)d_in[4];
    const float* b_out = (const float*)d_in[5];
    float* out = (float*)d_out;

    float *part, *rs, *sinv;
    bf16 *fhi, *flo, *dwhi, *dwlo, *qhi, *qlo, *khi, *klo, *vhi, *vlo;
    bf16 *avhi, *avlo, *chi, *clo, *wqh, *wql, *wph, *wpl, *woh, *wol;
    cudaGetSymbolAddress((void**)&part, g_part);
    cudaGetSymbolAddress((void**)&rs,   g_rs);
    cudaGetSymbolAddress((void**)&sinv, g_sinv);
    cudaGetSymbolAddress((void**)&fhi,  g_fhi);   cudaGetSymbolAddress((void**)&flo,  g_flo);
    cudaGetSymbolAddress((void**)&dwhi, g_dwhi);  cudaGetSymbolAddress((void**)&dwlo, g_dwlo);
    cudaGetSymbolAddress((void**)&qhi,  g_qhi);   cudaGetSymbolAddress((void**)&qlo,  g_qlo);
    cudaGetSymbolAddress((void**)&khi,  g_khi);   cudaGetSymbolAddress((void**)&klo,  g_klo);
    cudaGetSymbolAddress((void**)&vhi,  g_vhi);   cudaGetSymbolAddress((void**)&vlo,  g_vlo);
    cudaGetSymbolAddress((void**)&avhi, g_avhi);  cudaGetSymbolAddress((void**)&avlo, g_avlo);
    cudaGetSymbolAddress((void**)&chi,  g_ctxhi); cudaGetSymbolAddress((void**)&clo,  g_ctxlo);
    cudaGetSymbolAddress((void**)&wqh,  g_wqhi);  cudaGetSymbolAddress((void**)&wql,  g_wqlo);
    cudaGetSymbolAddress((void**)&wph,  g_wpwhi); cudaGetSymbolAddress((void**)&wpl,  g_wpwlo);
    cudaGetSymbolAddress((void**)&woh,  g_wohi);  cudaGetSymbolAddress((void**)&wol,  g_wolo);

    // 3-stage smem: A 3*2*BM*40*2  +  B 3*2*32*136*2
    const int SM128 = 3 * 2 * 128 * 40 * 2 + 3 * 2 * 32 * 136 * 2;  // 113664 B
    const int SM64  = 3 * 2 *  64 * 40 * 2 + 3 * 2 * 32 * 136 * 2;  //  82944 B
    const int SMCTX = 3 * 4 * 64 * 72 * 2;                          // 110592 B
    cudaFuncSetAttribute(k_mma_gemm<128,4>, cudaFuncAttributeMaxDynamicSharedMemorySize, SM128);
    cudaFuncSetAttribute(k_mma_gemm<128,6>, cudaFuncAttributeMaxDynamicSharedMemorySize, SM128);
    cudaFuncSetAttribute(k_mma_gemm<128,3>, cudaFuncAttributeMaxDynamicSharedMemorySize, SM128);
    cudaFuncSetAttribute(k_mma_gemm<64,2>,  cudaFuncAttributeMaxDynamicSharedMemorySize, SM64);
    cudaFuncSetAttribute(k_ctx_t,           cudaFuncAttributeMaxDynamicSharedMemorySize, SMCTX);

    // 0) weight splits
    k_cvt<<<512, 256>>>(w_q, wqh, wql, 512 * 256);
    k_cvt<<<1024, 256>>>(w_pw, wph, wpl, 1024 * 256);
    k_cvt<<<512, 256>>>(w_out, woh, wol, 256 * 512);

    // 1) depthwise 3x3 + fmap/dw hi-lo planes
    k_dwconv<<<dim3(16, BATCH * 256), 256>>>(fmap, w_dw);

    // 2) q = softmax_d(w_q @ fmap) * 1/8  (fused, hl out)
    k_mma_gemm<128, 4><<<dim3(128, 4, 8), 256, SM128>>>(
        wqh, wql, fhi, flo, nullptr, nullptr, nullptr, qhi, qlo, nullptr, nullptr,
        256, 0, 256LL * N_PIX, 512LL * N_PIX);

    // 3) fused kv: rows<512 -> exp(k)+rowsums; rows>=512 -> v  (hl out)
    k_mma_gemm<128, 6><<<dim3(128, 8, 8), 256, SM128>>>(
        wph, wpl, dwhi, dwlo, nullptr, rs, nullptr, khi, klo, vhi, vlo,
        256, 0, 256LL * N_PIX, 512LL * N_PIX);

    // 4) softmax-N normalizer: 1/S per k-row
    k_sumred<<<512, 256>>>(rs, sinv);

    // 5) context: pipelined tensor split-K partials + normalize-reduce
    k_ctx_t<<<512, 256, SMCTX>>>(khi, klo, vhi, vlo, part);
    k_ctx_reduce<<<1024, 256>>>(part, sinv, chi, clo);

    // 6) av = gelu(ctx^T @ q)  batched over 64 (b,h)  (hl out)
    k_mma_gemm<64, 2><<<dim3(128, 1, 64), 256, SM64>>>(
        chi, clo, qhi, qlo, nullptr, nullptr, nullptr, avhi, avlo, nullptr, nullptr,
        64, 4096LL, 64LL * N_PIX, 64LL * N_PIX);

    // 7) out = w_out @ av + b_out  (fp32 + bias)
    k_mma_gemm<128, 3><<<dim3(128, 2, 8), 256, SM128>>>(
        woh, wol, avhi, avlo, b_out, nullptr, out, nullptr, nullptr, nullptr, nullptr,
        512, 0, 512LL * N_PIX, 256LL * N_PIX);
}